// round 12
// baseline (speedup 1.0000x reference)
#include <cuda_runtime.h>
#include <cuda_fp16.h>
#include <cstdint>

#define NN 50000
#define EE 800000
#define HH 8
#define HD 128
#define CCOLS 40
#define CAP 64            // padded-CSR slots per node; P(Poisson(16) > 64) ~ 1e-19

// ---------------- scratch -------------------------------------------------
__device__ __align__(16) __half g_x16[NN * HD];     // fp16 activations
__device__ __align__(16) __half g_hp[NN * HD];      // fp16 projected features
__device__ __align__(16) __half g_w16[2 * HD * HD]; // fp16 weights, both layers
__device__ float  g_el[NN * HH];
__device__ float  g_er[NN * HH];
__device__ int    g_wr[NN];                          // cursor during fill; degree after
__device__ __align__(16) int g_csrc[NN * CAP + CAP]; // padded CSR (zero-init: pad slots = node 0)

// ---------------- convert: feats + Ws -> fp16 -------------------------------
__global__ void convert_kernel(const float* __restrict__ feats,
                               const float* __restrict__ Ws) {
    int i = blockIdx.x * blockDim.x + threadIdx.x;
    if (i < NN * HD / 4) {
        float4 v = ((const float4*)feats)[i];
        __half2 h0 = __floats2half2_rn(v.x, v.y);
        __half2 h1 = __floats2half2_rn(v.z, v.w);
        ((uint2*)g_x16)[i] = make_uint2(*(uint32_t*)&h0, *(uint32_t*)&h1);
    }
    if (i < 2 * HD * HD / 4) {
        float4 v = ((const float4*)Ws)[i];
        __half2 h0 = __floats2half2_rn(v.x, v.y);
        __half2 h1 = __floats2half2_rn(v.z, v.w);
        ((uint2*)g_w16)[i] = make_uint2(*(uint32_t*)&h0, *(uint32_t*)&h1);
    }
}

// ---------------- padded-CSR fill (no count, no scan) -----------------------
__global__ void fill_csr_kernel(const int* __restrict__ src, const int* __restrict__ dst) {
    int e4 = blockIdx.x * blockDim.x + threadIdx.x;
    if (e4 * 4 < EE) {
        int4 d = ((const int4*)dst)[e4];
        int4 s = ((const int4*)src)[e4];
        g_csrc[(d.x << 6) + atomicAdd(&g_wr[d.x], 1)] = s.x;
        g_csrc[(d.y << 6) + atomicAdd(&g_wr[d.y], 1)] = s.y;
        g_csrc[(d.z << 6) + atomicAdd(&g_wr[d.z], 1)] = s.z;
        g_csrc[(d.w << 6) + atomicAdd(&g_wr[d.w], 1)] = s.w;
    }
}

// ---------------- fp16 tensor-core GEMM (cp.async) + fused el/er ------------
__device__ __forceinline__ uint32_t smem_u32(const void* p) {
    return (uint32_t)__cvta_generic_to_shared(p);
}

__device__ __forceinline__ void cp_async16(uint32_t saddr, const void* gptr, bool pred) {
    int bytes = pred ? 16 : 0;
    asm volatile("cp.async.cg.shared.global [%0], [%1], 16, %2;\n"
                 :: "r"(saddr), "l"(gptr), "r"(bytes));
}

__device__ __forceinline__ void ldmatrix_x4(uint32_t* d, uint32_t addr) {
    asm volatile("ldmatrix.sync.aligned.m8n8.x4.shared.b16 {%0,%1,%2,%3}, [%4];"
                 : "=r"(d[0]), "=r"(d[1]), "=r"(d[2]), "=r"(d[3]) : "r"(addr));
}

__device__ __forceinline__ void ldmatrix_x4_trans(uint32_t* d, uint32_t addr) {
    asm volatile("ldmatrix.sync.aligned.m8n8.x4.trans.shared.b16 {%0,%1,%2,%3}, [%4];"
                 : "=r"(d[0]), "=r"(d[1]), "=r"(d[2]), "=r"(d[3]) : "r"(addr));
}

__device__ __forceinline__ void mma_f16(float* c, const uint32_t* a,
                                        uint32_t b0, uint32_t b1) {
    asm volatile(
        "mma.sync.aligned.m16n8k16.row.col.f32.f16.f16.f32 "
        "{%0,%1,%2,%3}, {%4,%5,%6,%7}, {%8,%9}, {%0,%1,%2,%3};"
        : "+f"(c[0]), "+f"(c[1]), "+f"(c[2]), "+f"(c[3])
        : "r"(a[0]), "r"(a[1]), "r"(a[2]), "r"(a[3]), "r"(b0), "r"(b1));
}

#define GEMM_SMEM (64 * 136 * 2 + 128 * 136 * 2)
__global__ __launch_bounds__(256, 4) void gemm_h16_kernel(
    const __half* __restrict__ A, const __half* __restrict__ W, __half* __restrict__ C,
    const float* __restrict__ al, const float* __restrict__ ar) {
    extern __shared__ char dyn_smem[];
    __half(*As)[136]  = (__half(*)[136])dyn_smem;
    __half(*Wsh)[136] = (__half(*)[136])(dyn_smem + 64 * 136 * 2);
    float(*s_el)[8] = (float(*)[8])dyn_smem;                   // alias (post-compute)
    float(*s_er)[8] = (float(*)[8])(dyn_smem + 64 * 8 * 4);
    int tid = threadIdx.x;
    int wid = tid >> 5;
    int lane = tid & 31;
    int g = lane >> 2;
    int tig = lane & 3;
    int warpRow = wid & 1;
    int warpCol = wid >> 1;
    int row0 = blockIdx.x << 6;

    #pragma unroll
    for (int i = 0; i < 4; i++) {
        int idx = tid + (i << 8);
        int r = idx >> 4;
        int c16 = idx & 15;
        cp_async16(smem_u32(&As[r][c16 * 8]),
                   A + (size_t)(row0 + r) * 128 + c16 * 8,
                   (row0 + r) < NN);
    }
    #pragma unroll
    for (int i = 0; i < 8; i++) {
        int idx = tid + (i << 8);
        int k = idx >> 4;
        int c16 = idx & 15;
        cp_async16(smem_u32(&Wsh[k][c16 * 8]), W + k * 128 + c16 * 8, true);
    }
    asm volatile("cp.async.commit_group;");

    float c[2][4][4];
    #pragma unroll
    for (int sm = 0; sm < 2; sm++)
        #pragma unroll
        for (int sn = 0; sn < 4; sn++)
            #pragma unroll
            for (int q = 0; q < 4; q++) c[sm][sn][q] = 0.f;

    asm volatile("cp.async.wait_group 0;");
    __syncthreads();

    #pragma unroll
    for (int kk = 0; kk < 128; kk += 16) {
        uint32_t a[2][4], b[2][4];
        #pragma unroll
        for (int sm = 0; sm < 2; sm++) {
            int r = warpRow * 32 + sm * 16 + (lane & 15);
            ldmatrix_x4(a[sm], smem_u32(&As[r][kk + ((lane >> 4) << 3)]));
        }
        #pragma unroll
        for (int nb = 0; nb < 2; nb++) {
            int col = warpCol * 32 + nb * 16 + ((lane >> 4) << 3);
            ldmatrix_x4_trans(b[nb], smem_u32(&Wsh[kk + (lane & 15)][col]));
        }
        #pragma unroll
        for (int sm = 0; sm < 2; sm++)
            #pragma unroll
            for (int sn = 0; sn < 4; sn++)
                mma_f16(c[sm][sn], a[sm],
                        b[sn >> 1][(sn & 1) * 2], b[sn >> 1][(sn & 1) * 2 + 1]);
    }
    __syncthreads();   // done with As/Wsh; s_el/s_er alias now

    float alr[4][2], arr[4][2];
    #pragma unroll
    for (int sn = 0; sn < 4; sn++) {
        int col = warpCol * 32 + sn * 8 + tig * 2;
        alr[sn][0] = al[col];     alr[sn][1] = al[col + 1];
        arr[sn][0] = ar[col];     arr[sn][1] = ar[col + 1];
    }
    #pragma unroll
    for (int sm = 0; sm < 2; sm++) {
        int rbase = row0 + warpRow * 32 + sm * 16 + g;
        #pragma unroll
        for (int sn = 0; sn < 4; sn++) {
            int col = warpCol * 32 + sn * 8 + tig * 2;
            if (rbase < NN)
                *(__half2*)&C[rbase * 128 + col] =
                    __floats2half2_rn(c[sm][sn][0], c[sm][sn][1]);
            if (rbase + 8 < NN)
                *(__half2*)&C[(rbase + 8) * 128 + col] =
                    __floats2half2_rn(c[sm][sn][2], c[sm][sn][3]);
        }
        #pragma unroll
        for (int hh = 0; hh < 2; hh++) {
            #pragma unroll
            for (int ro = 0; ro < 2; ro++) {
                float pel = 0.f, per = 0.f;
                #pragma unroll
                for (int sni = 0; sni < 2; sni++) {
                    int sn = hh * 2 + sni;
                    #pragma unroll
                    for (int qq = 0; qq < 2; qq++) {
                        float cv = c[sm][sn][ro * 2 + qq];
                        pel = fmaf(cv, alr[sn][qq], pel);
                        per = fmaf(cv, arr[sn][qq], per);
                    }
                }
                pel += __shfl_xor_sync(0xFFFFFFFFu, pel, 1);
                pel += __shfl_xor_sync(0xFFFFFFFFu, pel, 2);
                per += __shfl_xor_sync(0xFFFFFFFFu, per, 1);
                per += __shfl_xor_sync(0xFFFFFFFFu, per, 2);
                if (tig == 0) {
                    int r = warpRow * 32 + sm * 16 + g + ro * 8;
                    int h = warpCol * 2 + hh;
                    s_el[r][h] = pel;
                    s_er[r][h] = per;
                }
            }
        }
    }
    __syncthreads();
    #pragma unroll
    for (int q = 0; q < 2; q++) {
        int idx = tid + (q << 8);
        int r = idx >> 3, h = idx & 7;
        if (row0 + r < NN) {
            g_el[(row0 + r) * 8 + h] = s_el[r][h];
            g_er[(row0 + r) * 8 + h] = s_er[r][h];
        }
    }
}

// ---------------- fused: edge-softmax aggregate + bias + LN + ReLU ----------
// warp per node. Weight math de-duplicated: lane tig computes weights for
// edges 2*tig, 2*tig+1 of its head quad, then shfl-broadcast. Padded batches
// (weights predicated to 0 for k >= deg; pad indices are 0 = valid row).
__global__ __launch_bounds__(256) void gat_agg_kernel(
    const __half* __restrict__ hp,
    const float* __restrict__ bias, const float* __restrict__ gamma,
    const float* __restrict__ beta, __half* __restrict__ hout) {
    int n = blockIdx.x * 8 + (threadIdx.x >> 5);
    if (n >= NN) return;
    int lane = threadIdx.x & 31;
    int quad = lane >> 2;           // head
    int tig = lane & 3;
    float er_h = g_er[n * 8 + quad];
    int cnt = g_wr[n];
    int nb = (cnt + 7) >> 3;        // padded 8-edge batches
    const uint2* __restrict__ hp2 = (const uint2*)hp;
    const int4* __restrict__ cs4 = (const int4*)g_csrc;
    int base4 = n << 4;             // int4 index of this node's CSR row

    float ax = 0.f, ay = 0.f, az = 0.f, aw = 0.f, s_part = 0.f;
    int e0 = tig * 2, e1 = e0 + 1;
    for (int b = 0; b < nb; b++) {
        int4 i0 = cs4[base4 + b * 2];
        int4 i1 = cs4[base4 + b * 2 + 1];
        int idx[8] = {i0.x, i0.y, i0.z, i0.w, i1.x, i1.y, i1.z, i1.w};
        // hp loads first (MLP)
        uint2 v[8];
        #pragma unroll
        for (int u = 0; u < 8; u++) v[u] = hp2[idx[u] * 32 + lane];
        // weight phase: 2 edges per lane (others' heads get theirs via shfl)
        int j0 = b * 8;
        float q0 = g_el[idx[e0] * 8 + quad] + er_h;
        float q1 = g_el[idx[e1] * 8 + quad] + er_h;
        q0 = (q0 > 0.f) ? q0 : 0.2f * q0;
        q1 = (q1 > 0.f) ? q1 : 0.2f * q1;
        float w0 = (j0 + e0 < cnt) ? __expf(q0) : 0.f;
        float w1 = (j0 + e1 < cnt) ? __expf(q1) : 0.f;
        s_part += w0 + w1;
        float we[8];
        #pragma unroll
        for (int e = 0; e < 8; e++)
            we[e] = __shfl_sync(0xFFFFFFFFu, (e & 1) ? w1 : w0,
                                (quad << 2) + (e >> 1));
        #pragma unroll
        for (int u = 0; u < 8; u++) {
            float2 f0 = __half22float2(*(__half2*)&v[u].x);
            float2 f1 = __half22float2(*(__half2*)&v[u].y);
            ax = fmaf(we[u], f0.x, ax);
            ay = fmaf(we[u], f0.y, ay);
            az = fmaf(we[u], f1.x, az);
            aw = fmaf(we[u], f1.y, aw);
        }
    }
    // per-head softmax denominator: reduce partials across the quad
    float s = s_part;
    s += __shfl_xor_sync(0xFFFFFFFFu, s, 1);
    s += __shfl_xor_sync(0xFFFFFFFFu, s, 2);

    float inv = 1.f / (s + 1e-16f);
    float4 b4  = ((const float4*)bias)[lane];
    float4 g4  = ((const float4*)gamma)[lane];
    float4 be4 = ((const float4*)beta)[lane];
    float ox = fmaf(ax, inv, b4.x);
    float oy = fmaf(ay, inv, b4.y);
    float oz = fmaf(az, inv, b4.z);
    float ow = fmaf(aw, inv, b4.w);

    float sum = (ox + oy) + (oz + ow);
    #pragma unroll
    for (int off = 16; off >= 1; off >>= 1) sum += __shfl_xor_sync(0xFFFFFFFFu, sum, off);
    float mu = sum * 0.0078125f;
    float dx = ox - mu, dy = oy - mu, dz = oz - mu, dw = ow - mu;
    float sq = (dx * dx + dy * dy) + (dz * dz + dw * dw);
    #pragma unroll
    for (int off = 16; off >= 1; off >>= 1) sq += __shfl_xor_sync(0xFFFFFFFFu, sq, off);
    float rstd = rsqrtf(sq * 0.0078125f + 1e-5f);
    __half2 o0 = __floats2half2_rn(
        fmaxf(fmaf(dx * rstd, g4.x, be4.x), 0.f),
        fmaxf(fmaf(dy * rstd, g4.y, be4.y), 0.f));
    __half2 o1 = __floats2half2_rn(
        fmaxf(fmaf(dz * rstd, g4.z, be4.z), 0.f),
        fmaxf(fmaf(dw * rstd, g4.w, be4.w), 0.f));
    ((uint2*)hout)[n * 32 + lane] = make_uint2(*(uint32_t*)&o0, *(uint32_t*)&o1);
}

// ---------------- final projection: out[N,40] = h16[N,128] @ Wp + bp --------
__global__ __launch_bounds__(160) void pred_kernel(
    const __half* __restrict__ hfeat, const float* __restrict__ Wp,
    const float* __restrict__ bp, float* __restrict__ out) {
    __shared__ float Hs[64][68];
    __shared__ float Wsh[64][40];
    int tid = threadIdx.x;
    int ci = tid % 10;
    int j  = tid / 10;
    int n0 = blockIdx.x << 6;
    float acc[4][4];
    #pragma unroll
    for (int r = 0; r < 4; r++)
        #pragma unroll
        for (int c = 0; c < 4; c++) acc[r][c] = 0.f;

    for (int kc = 0; kc < 128; kc += 64) {
        for (int idx = tid; idx < 64 * 32; idx += 160) {
            int n = idx >> 5;
            int k2 = idx & 31;
            int gn = n0 + n;
            float2 f = (gn < NN)
                ? __half22float2(*(const __half2*)&hfeat[gn * 128 + kc + k2 * 2])
                : make_float2(0.f, 0.f);
            Hs[k2 * 2][n]     = f.x;
            Hs[k2 * 2 + 1][n] = f.y;
        }
        for (int idx = tid; idx < 64 * 40; idx += 160) {
            int k = idx / 40;
            int c = idx - k * 40;
            Wsh[k][c] = Wp[(kc + k) * 40 + c];
        }
        __syncthreads();
        #pragma unroll
        for (int k = 0; k < 64; k++) {
            float4 a = *(const float4*)&Hs[k][j * 4];
            float4 b = *(const float4*)&Wsh[k][ci * 4];
            float av[4] = {a.x, a.y, a.z, a.w};
            float bv[4] = {b.x, b.y, b.z, b.w};
            #pragma unroll
            for (int r = 0; r < 4; r++)
                #pragma unroll
                for (int c = 0; c < 4; c++)
                    acc[r][c] = fmaf(av[r], bv[c], acc[r][c]);
        }
        __syncthreads();
    }
    #pragma unroll
    for (int r = 0; r < 4; r++) {
        int gn = n0 + j * 4 + r;
        if (gn < NN) {
            #pragma unroll
            for (int c = 0; c < 4; c++)
                out[gn * CCOLS + ci * 4 + c] = acc[r][c] + bp[ci * 4 + c];
        }
    }
}

// ---------------- launch ----------------------------------------------------
extern "C" void kernel_launch(void* const* d_in, const int* in_sizes, int n_in,
                              void* d_out, int out_size) {
    const float* feats = (const float*)d_in[0];
    const int*   src   = (const int*)d_in[1];
    const int*   dst   = (const int*)d_in[2];
    const float* Ws    = (const float*)d_in[3];
    const float* al    = (const float*)d_in[4];
    const float* ar    = (const float*)d_in[5];
    const float* bias  = (const float*)d_in[6];
    const float* gamma = (const float*)d_in[7];
    const float* beta  = (const float*)d_in[8];
    const float* Wp    = (const float*)d_in[9];
    const float* bp    = (const float*)d_in[10];
    float* out = (float*)d_out;

    __half* x16; cudaGetSymbolAddress((void**)&x16, g_x16);
    __half* hp;  cudaGetSymbolAddress((void**)&hp, g_hp);
    __half* w16; cudaGetSymbolAddress((void**)&w16, g_w16);
    int* wr;     cudaGetSymbolAddress((void**)&wr, g_wr);

    static cudaStream_t s2 = nullptr;
    static cudaEvent_t evFork = nullptr, evJoin = nullptr;
    if (s2 == nullptr) {
        cudaStreamCreateWithFlags(&s2, cudaStreamNonBlocking);
        cudaEventCreateWithFlags(&evFork, cudaEventDisableTiming);
        cudaEventCreateWithFlags(&evJoin, cudaEventDisableTiming);
        cudaFuncSetAttribute(gemm_h16_kernel,
                             cudaFuncAttributeMaxDynamicSharedMemorySize, GEMM_SMEM);
    }

    // fork: padded-CSR build (memset + fill only) on s2, hidden under
    // convert + layer-0 GEMM on the main stream.
    cudaEventRecord(evFork, 0);
    cudaStreamWaitEvent(s2, evFork, 0);
    cudaMemsetAsync(wr, 0, NN * sizeof(int), s2);
    fill_csr_kernel<<<(EE / 4 + 255) / 256, 256, 0, s2>>>(src, dst);
    cudaEventRecord(evJoin, s2);

    convert_kernel<<<(NN * HD / 4 + 255) / 256, 256>>>(feats, Ws);

    const int gemm_blocks = (NN + 63) / 64;  // 782
    gemm_h16_kernel<<<gemm_blocks, 256, GEMM_SMEM>>>(x16, w16, hp, al, ar);
    cudaStreamWaitEvent(0, evJoin, 0);       // join before aggregation
    gat_agg_kernel<<<(NN + 7) / 8, 256>>>(hp, bias, gamma, beta, x16);

    gemm_h16_kernel<<<gemm_blocks, 256, GEMM_SMEM>>>(x16, w16 + HD * HD, hp,
                                                     al + 128, ar + 128);
    gat_agg_kernel<<<(NN + 7) / 8, 256>>>(hp, bias + 128, gamma + 128,
                                          beta + 128, x16);

    pred_kernel<<<gemm_blocks, 160>>>(x16, Wp, bp, out);
}